// round 14
// baseline (speedup 1.0000x reference)
#include <cuda_runtime.h>
#include <math.h>

#define BB 128
#define TT 512
#define WW 64
#define DD 128
#define CC 256
#define KS 12
#define TP 500

typedef unsigned long long ull;
typedef unsigned int uint;

// ---------------- device scratch (no runtime allocation allowed) ----------------
__device__ float g_z[(size_t)BB * TT * DD];        // 33.5 MB  (B,T,D) normalized z
__device__ float g_xp[(size_t)BB * TT * 3 * CC];   // 201 MB   (B,T,768) x_proj
__device__ float g_c[(size_t)BB * TT * CC];        // 67 MB    (B,T,C) GRU hidden states
__device__ float g_whT[3 * CC * CC];               // Wh transposed: [col][k]
__device__ double g_loss;
__device__ int    g_cnt;

__device__ __forceinline__ uint f2tf(float f) {
    uint u;
    asm("cvt.rna.tf32.f32 %0, %1;" : "=r"(u) : "f"(f));
    return u;
}
__device__ __forceinline__ ull ffma2(ull a, ull b, ull c) {
    ull d;
    asm("fma.rn.f32x2 %0, %1, %2, %3;" : "=l"(d) : "l"(a), "l"(b), "l"(c));
    return d;
}
__device__ __forceinline__ ull packf2(float lo, float hi) {
    ull d;
    asm("mov.b64 %0, {%1, %2};" : "=l"(d) : "f"(lo), "f"(hi));
    return d;
}
__device__ __forceinline__ float pairsum(ull v) {
    float lo, hi;
    asm("mov.b64 {%0, %1}, %2;" : "=f"(lo), "=f"(hi) : "l"(v));
    return lo + hi;
}
__device__ __forceinline__ void unpackf2(ull v, float& lo, float& hi) {
    asm("mov.b64 {%0, %1}, %2;" : "=f"(lo), "=f"(hi) : "l"(v));
}
__device__ __forceinline__ uint sm32(const void* p) {
    uint a;
    asm("{ .reg .u64 t; cvta.to.shared.u64 t, %1; cvt.u32.u64 %0, t; }"
        : "=r"(a) : "l"(p));
    return a;
}
#define MMA_TF32(d, a, b) \
    asm volatile("mma.sync.aligned.m16n8k8.row.col.f32.tf32.tf32.f32 " \
                 "{%0,%1,%2,%3},{%4,%5,%6,%7},{%8,%9},{%0,%1,%2,%3};" \
                 : "+f"((d)[0]), "+f"((d)[1]), "+f"((d)[2]), "+f"((d)[3]) \
                 : "r"((a)[0]), "r"((a)[1]), "r"((a)[2]), "r"((a)[3]), \
                   "r"((b)[0]), "r"((b)[1]))

// ---------------- z = l2norm(rr @ We + be)  (+ fused init + Wh transpose) ----------------
__global__ __launch_bounds__(128) void k_z(const float* __restrict__ rr,
                                           const float* __restrict__ We,
                                           const float* __restrict__ be,
                                           const float* __restrict__ Wh) {
    __shared__ float Wes[64 * 128];
    __shared__ float rs[64];
    __shared__ float red[4];
    int b = blockIdx.y;
    int t0 = blockIdx.x << 6;
    int tid = threadIdx.x;

    int gb = blockIdx.y * 8 + blockIdx.x;
    int gtid = gb * 128 + tid;
    if (gtid == 0) { g_loss = 0.0; g_cnt = 0; }
    for (int i = gtid; i < 3 * CC * CC; i += 131072) {
        int kk = i & 255;
        int col = i >> 8;
        g_whT[i] = Wh[(size_t)kk * 768 + col];
    }

    for (int i = tid; i < 64 * 128; i += 128) Wes[i] = We[i];
    float bias = be[tid];
    __syncthreads();
    for (int tt = 0; tt < 64; tt++) {
        int t = t0 + tt;
        if (tid < 64) rs[tid] = rr[((size_t)b * TT + t) * WW + tid];
        __syncthreads();
        float acc = bias;
#pragma unroll
        for (int w = 0; w < 64; w++) acc += rs[w] * Wes[w * 128 + tid];
        float ss = acc * acc;
#pragma unroll
        for (int o = 16; o; o >>= 1) ss += __shfl_xor_sync(0xffffffffu, ss, o);
        if ((tid & 31) == 0) red[tid >> 5] = ss;
        __syncthreads();
        float tot = red[0] + red[1] + red[2] + red[3];
        float scale = 1.0f / fmaxf(sqrtf(tot), 1e-12f);
        g_z[((size_t)b * TT + t) * DD + tid] = acc * scale;
        __syncthreads();
    }
}

// ---------------- x_proj = z @ Wi + bi  (M=65536, N=768, K=128), FFMA2 ----------------
__global__ __launch_bounds__(256) void k_xproj(const float* __restrict__ Wi,
                                               const float* __restrict__ bi) {
    __shared__ float As[32 * 132];
    __shared__ float Bs[32 * 132];
    int tid = threadIdx.x;
    int tx = tid & 15, ty = tid >> 4;
    int m0 = blockIdx.y << 7, n0 = blockIdx.x << 7;
    ull accp[8][4];
#pragma unroll
    for (int i = 0; i < 8; i++)
#pragma unroll
        for (int p = 0; p < 4; p++) accp[i][p] = 0ull;

    for (int kc = 0; kc < DD; kc += 32) {
        for (int i = tid; i < 4096; i += 256) {
            int r = i >> 5, kk = i & 31;
            As[kk * 132 + r] = g_z[(size_t)(m0 + r) * DD + kc + kk];
        }
        for (int i = tid; i < 4096; i += 256) {
            int kk = i >> 7, n = i & 127;
            Bs[kk * 132 + n] = Wi[(size_t)(kc + kk) * 768 + n0 + n];
        }
        __syncthreads();
#pragma unroll
        for (int kk = 0; kk < 32; kk++) {
            float4 a1 = *(const float4*)&As[kk * 132 + ty * 4];
            float4 a2 = *(const float4*)&As[kk * 132 + 64 + ty * 4];
            ulonglong2 B1 = *(const ulonglong2*)&Bs[kk * 132 + tx * 4];
            ulonglong2 B2 = *(const ulonglong2*)&Bs[kk * 132 + 64 + tx * 4];
            float av[8] = {a1.x, a1.y, a1.z, a1.w, a2.x, a2.y, a2.z, a2.w};
#pragma unroll
            for (int i = 0; i < 8; i++) {
                ull a2i = packf2(av[i], av[i]);
                accp[i][0] = ffma2(a2i, B1.x, accp[i][0]);
                accp[i][1] = ffma2(a2i, B1.y, accp[i][1]);
                accp[i][2] = ffma2(a2i, B2.x, accp[i][2]);
                accp[i][3] = ffma2(a2i, B2.y, accp[i][3]);
            }
        }
        __syncthreads();
    }
#pragma unroll
    for (int i = 0; i < 8; i++) {
        int r = m0 + ((i < 4) ? ty * 4 + i : 64 + ty * 4 + i - 4);
#pragma unroll
        for (int p = 0; p < 4; p++) {
            int j0 = 2 * p;
            float lo, hi;
            unpackf2(accp[i][p], lo, hi);
            int c0 = n0 + ((j0 < 4) ? tx * 4 + j0 : 64 + tx * 4 + j0 - 4);
            g_xp[(size_t)r * 768 + c0]     = lo + bi[c0];
            g_xp[(size_t)r * 768 + c0 + 1] = hi + bi[c0 + 1];
        }
    }
}

// ---------------- persistent GRU: cluster row-groups, DSMEM h exchange ----------------
// grid (8, 16), cluster (8,1,1): the 8 col-CTAs of one row-group form a
// hardware cluster. Each step, every thread writes its h_new directly into
// all 8 CTAs' double-buffered hs via st.shared::cluster; one barrier.cluster
// per step replaces the L2 counter relay + staging loads. h values bit-exact
// vs R13 (same FFMA2 order / reduce).
#define GRU3_SMEM ((96 * 256 + 2 * 8 * 256 + 8 * 3 * 256) * 4)
__global__ void __cluster_dims__(8, 1, 1) __launch_bounds__(256, 1)
k_gru3(const float* __restrict__ bh) {
    extern __shared__ float sm[];
    float* ws   = sm;                              // [96 cols][64 float4], XOR-swizzled
    float* hs   = sm + 96 * 256;                   // [2][8][256] double-buffered h
    float* part = sm + 96 * 256 + 2 * 8 * 256;     // [8][3][256] k-octant partials

    int tid = threadIdx.x;
    int cgx = blockIdx.x;                          // cluster rank (col-group)
    int rb0 = blockIdx.y << 3;
    int cb0 = cgx << 5;

    // ---- load Wh slice once, swizzled ----
    for (int i = tid; i < 96 * 64; i += 256) {
        int bc = i >> 6, kgrp = i & 63;
        int gate = bc >> 5, ch = bc & 31;
        float4 v = *(const float4*)&g_whT[(size_t)(gate * 256 + cb0 + ch) * 256 + kgrp * 4];
        *(float4*)&ws[(bc * 64 + (kgrp ^ (bc & 7))) * 4] = v;
    }
    // ---- init h buffer 0 to zeros ----
    *(float4*)&hs[tid * 8]     = make_float4(0.f, 0.f, 0.f, 0.f);
    *(float4*)&hs[tid * 8 + 4] = make_float4(0.f, 0.f, 0.f, 0.f);
    __syncthreads();
    asm volatile("barrier.cluster.arrive.aligned;" ::: "memory");
    asm volatile("barrier.cluster.wait.aligned;" ::: "memory");

    int uc = tid & 31;
    int kh = tid >> 5;
    int cg = cb0 + uc;
    float bhr = bh[cg], bhz = bh[256 + cg], bhn = bh[512 + cg];

    int ur = kh;
    int b  = rb0 + ur;
    const float* xpb = g_xp + (size_t)b * TT * 768;
    float* crow = g_c + (size_t)b * TT * CC;

    const ulonglong2* ws4 = (const ulonglong2*)ws;
    int s7 = uc & 7;
    int wb0 = (0  + uc) * 64 + kh * 8;
    int wb1 = (32 + uc) * 64 + kh * 8;
    int wb2 = (64 + uc) * 64 + kh * 8;

    int p = 0;
    for (int t = 0; t < TT; t++) {
        const float* hsP = hs + p * 2048;
        float* hsN = hs + (p ^ 1) * 2048;

        // prefetch x_proj (latency hidden under compute)
        float xr = __ldg(&xpb[(size_t)t * 768 + cg]);
        float xz = __ldg(&xpb[(size_t)t * 768 + 256 + cg]);
        float xn = __ldg(&xpb[(size_t)t * 768 + 512 + cg]);

        // ---- h @ Wh via packed f32x2 FMA; W de-swizzled to logical j ----
        ull p0[8], p1[8], p2[8];
#pragma unroll
        for (int r = 0; r < 8; r++) { p0[r] = 0ull; p1[r] = 0ull; p2[r] = 0ull; }
#pragma unroll
        for (int j = 0; j < 8; j++) {
            int js = j ^ s7;
            ulonglong2 W0 = ws4[wb0 + js];
            ulonglong2 W1 = ws4[wb1 + js];
            ulonglong2 W2 = ws4[wb2 + js];
            int kofs = kh * 32 + j * 4;
#pragma unroll
            for (int r = 0; r < 8; r++) {
                ulonglong2 H = *(const ulonglong2*)&hsP[r * 256 + kofs];
                p0[r] = ffma2(H.x, W0.x, p0[r]);
                p0[r] = ffma2(H.y, W0.y, p0[r]);
                p1[r] = ffma2(H.x, W1.x, p1[r]);
                p1[r] = ffma2(H.y, W1.y, p1[r]);
                p2[r] = ffma2(H.x, W2.x, p2[r]);
                p2[r] = ffma2(H.y, W2.y, p2[r]);
            }
        }
#pragma unroll
        for (int r = 0; r < 8; r++) {
            part[(r * 3 + 0) * 256 + kh * 32 + uc] = pairsum(p0[r]);
            part[(r * 3 + 1) * 256 + kh * 32 + uc] = pairsum(p1[r]);
            part[(r * 3 + 2) * 256 + kh * 32 + uc] = pairsum(p2[r]);
        }
        __syncthreads();

        // ---- reduce + gates + state update: thread (ur, uc) ----
        float hnew;
        {
            float hr = bhr, hz = bhz, hn = bhn;
#pragma unroll
            for (int q = 0; q < 8; q++) {
                hr += part[(ur * 3 + 0) * 256 + q * 32 + uc];
                hz += part[(ur * 3 + 1) * 256 + q * 32 + uc];
                hn += part[(ur * 3 + 2) * 256 + q * 32 + uc];
            }
            float rgt = 1.f / (1.f + expf(-(xr + hr)));
            float zgt = 1.f / (1.f + expf(-(xz + hz)));
            float ngt = tanhf(xn + rgt * hn);
            float hp = hsP[ur * 256 + cg];
            hnew = (1.f - zgt) * ngt + zgt * hp;
            crow[(size_t)t * CC + cg] = hnew;   // fire-and-forget (read by later kernels)
        }

        // ---- broadcast h_new into all 8 cluster CTAs' next-buffer ----
        {
            uint laddr = sm32(&hsN[ur * 256 + cg]);
#pragma unroll
            for (int rk = 0; rk < 8; rk++) {
                uint ra;
                asm volatile("mapa.shared::cluster.u32 %0, %1, %2;"
                             : "=r"(ra) : "r"(laddr), "r"(rk));
                asm volatile("st.shared::cluster.f32 [%0], %1;"
                             :: "r"(ra), "f"(hnew) : "memory");
            }
        }
        asm volatile("barrier.cluster.arrive.aligned;" ::: "memory");
        asm volatile("barrier.cluster.wait.aligned;" ::: "memory");
        p ^= 1;
    }
}

// ---------------- fused loss: tf32 mma, 512 threads, reg-prefetch staging ----------------
#define LOSS_SMEM ((128 * 132 + 128 * 132 + 128 + 64) * 4)
__global__ __launch_bounds__(512) void k_loss(const float* __restrict__ Wkw,
                                              const float* __restrict__ Wkb) {
    extern __shared__ float sm[];
    float* Psm = sm;                     // [128][132]
    float* As  = sm + 128 * 132;         // [128][36]  (stage1 A, tf32)
    float* Bs  = As + 128 * 36;          // [32][136]  (stage1 B, tf32)
    float* Zsm = sm + 128 * 132;         // [128][132] (stage2, aliases As/Bs)
    float* rnorm = sm + 2 * 128 * 132;
    float* red = rnorm + 128;            // 16 floats + 16 ints

    int t = blockIdx.x, k = blockIdx.y;
    int tid = threadIdx.x;
    int lane = tid & 31, wid = tid >> 5;
    int g = lane >> 2, tq = lane & 3;
    int R0 = (wid >> 2) * 32;
    int C0 = (wid & 3) * 32;

    int ar[8], ak[8], bk[8], bd[8];
#pragma unroll
    for (int j = 0; j < 8; j++) {
        int i = tid + j * 512;
        ar[j] = i >> 5;  ak[j] = i & 31;
        bk[j] = i >> 7;  bd[j] = i & 127;
    }

    float acc[2][4][4];
#pragma unroll
    for (int mt = 0; mt < 2; mt++)
#pragma unroll
        for (int nt = 0; nt < 4; nt++)
#pragma unroll
            for (int i = 0; i < 4; i++) acc[mt][nt][i] = 0.f;

    float ra[8], rb[8];
#pragma unroll
    for (int j = 0; j < 8; j++) {
        ra[j] = g_c[((size_t)ar[j] * TT + t) * CC + ak[j]];
        rb[j] = Wkw[((size_t)k * CC + bk[j]) * DD + bd[j]];
    }

    for (int kc = 0; kc < CC; kc += 32) {
#pragma unroll
        for (int j = 0; j < 8; j++) {
            As[ar[j] * 36 + ak[j]]  = __uint_as_float(f2tf(ra[j]));
            Bs[bk[j] * 136 + bd[j]] = __uint_as_float(f2tf(rb[j]));
        }
        __syncthreads();
        if (kc + 32 < CC) {
#pragma unroll
            for (int j = 0; j < 8; j++) {
                ra[j] = g_c[((size_t)ar[j] * TT + t) * CC + kc + 32 + ak[j]];
                rb[j] = Wkw[((size_t)k * CC + kc + 32 + bk[j]) * DD + bd[j]];
            }
        }
#pragma unroll
        for (int ks = 0; ks < 4; ks++) {
            int k0 = ks * 8;
            uint af[2][4];
#pragma unroll
            for (int mt = 0; mt < 2; mt++) {
                int r = R0 + mt * 16 + g;
                af[mt][0] = __float_as_uint(As[r * 36 + k0 + tq]);
                af[mt][1] = __float_as_uint(As[(r + 8) * 36 + k0 + tq]);
                af[mt][2] = __float_as_uint(As[r * 36 + k0 + tq + 4]);
                af[mt][3] = __float_as_uint(As[(r + 8) * 36 + k0 + tq + 4]);
            }
            uint bf[4][2];
#pragma unroll
            for (int nt = 0; nt < 4; nt++) {
                int c = C0 + nt * 8 + g;
                bf[nt][0] = __float_as_uint(Bs[(k0 + tq) * 136 + c]);
                bf[nt][1] = __float_as_uint(Bs[(k0 + tq + 4) * 136 + c]);
            }
#pragma unroll
            for (int mt = 0; mt < 2; mt++)
#pragma unroll
                for (int nt = 0; nt < 4; nt++) MMA_TF32(acc[mt][nt], af[mt], bf[nt]);
        }
        __syncthreads();
    }

#pragma unroll
    for (int nt = 0; nt < 4; nt++) {
        int c0 = C0 + nt * 8 + 2 * tq;
        float bia0 = __ldg(&Wkb[k * DD + c0]);
        float bia1 = __ldg(&Wkb[k * DD + c0 + 1]);
#pragma unroll
        for (int mt = 0; mt < 2; mt++) {
            int r = R0 + mt * 16 + g;
            Psm[r * 132 + c0]           = __uint_as_float(f2tf(acc[mt][nt][0] + bia0));
            Psm[r * 132 + c0 + 1]       = __uint_as_float(f2tf(acc[mt][nt][1] + bia1));
            Psm[(r + 8) * 132 + c0]     = __uint_as_float(f2tf(acc[mt][nt][2] + bia0));
            Psm[(r + 8) * 132 + c0 + 1] = __uint_as_float(f2tf(acc[mt][nt][3] + bia1));
        }
    }
    __syncthreads();

    for (int i = tid; i < 16384; i += 512) {
        int cidx = i >> 7, d = i & 127;
        Zsm[cidx * 132 + d] =
            __uint_as_float(f2tf(g_z[((size_t)cidx * TT + t + k + 1) * DD + d]));
    }
    if (tid < 128) {
        const float4* pp = (const float4*)&Psm[tid * 132];
        float ss = 0.f;
#pragma unroll
        for (int q = 0; q < 32; q++) {
            float4 v = pp[q];
            ss += v.x * v.x + v.y * v.y + v.z * v.z + v.w * v.w;
        }
        rnorm[tid] = 1.f / fmaxf(sqrtf(ss), 1e-12f);
    }
    __syncthreads();

    float acc2[2][4][4];
#pragma unroll
    for (int mt = 0; mt < 2; mt++)
#pragma unroll
        for (int nt = 0; nt < 4; nt++)
#pragma unroll
            for (int i = 0; i < 4; i++) acc2[mt][nt][i] = 0.f;

#pragma unroll
    for (int ks = 0; ks < 16; ks++) {
        int k0 = ks * 8;
        uint af[2][4];
#pragma unroll
        for (int mt = 0; mt < 2; mt++) {
            int r = R0 + mt * 16 + g;
            af[mt][0] = __float_as_uint(Psm[r * 132 + k0 + tq]);
            af[mt][1] = __float_as_uint(Psm[(r + 8) * 132 + k0 + tq]);
            af[mt][2] = __float_as_uint(Psm[r * 132 + k0 + tq + 4]);
            af[mt][3] = __float_as_uint(Psm[(r + 8) * 132 + k0 + tq + 4]);
        }
        uint bf[4][2];
#pragma unroll
        for (int nt = 0; nt < 4; nt++) {
            int c = C0 + nt * 8 + g;
            bf[nt][0] = __float_as_uint(Zsm[c * 132 + k0 + tq]);
            bf[nt][1] = __float_as_uint(Zsm[c * 132 + k0 + tq + 4]);
        }
#pragma unroll
        for (int mt = 0; mt < 2; mt++)
#pragma unroll
            for (int nt = 0; nt < 4; nt++) MMA_TF32(acc2[mt][nt], af[mt], bf[nt]);
    }
    __syncthreads();

#pragma unroll
    for (int mt = 0; mt < 2; mt++) {
        int r = R0 + mt * 16 + g;
        float rn0 = rnorm[r] * 10.0f;
        float rn1 = rnorm[r + 8] * 10.0f;
#pragma unroll
        for (int nt = 0; nt < 4; nt++) {
            int c0 = C0 + nt * 8 + 2 * tq;
            Psm[r * 132 + c0]           = acc2[mt][nt][0] * rn0;
            Psm[r * 132 + c0 + 1]       = acc2[mt][nt][1] * rn0;
            Psm[(r + 8) * 132 + c0]     = acc2[mt][nt][2] * rn1;
            Psm[(r + 8) * 132 + c0 + 1] = acc2[mt][nt][3] * rn1;
        }
    }
    __syncthreads();

    float lossv = 0.f;
    int corr = 0;
    {
        int row = tid >> 2, sub = tid & 3;
        const float* L = &Psm[row * 132];
        int c0 = sub * 32;
        float m = -1e30f;
        int am = 0;
        for (int cc = c0; cc < c0 + 32; cc++) {
            float v = L[cc];
            if (v > m) { m = v; am = cc; }
        }
#pragma unroll
        for (int o = 1; o <= 2; o <<= 1) {
            float om = __shfl_xor_sync(0xffffffffu, m, o);
            int oa = __shfl_xor_sync(0xffffffffu, am, o);
            if (om > m || (om == m && oa < am)) { m = om; am = oa; }
        }
        float s = 0.f;
        for (int cc = c0; cc < c0 + 32; cc++) s += expf(L[cc] - m);
#pragma unroll
        for (int o = 1; o <= 2; o <<= 1) s += __shfl_xor_sync(0xffffffffu, s, o);
        if (sub == 0) {
            lossv = m + logf(s) - L[row];
            corr = (am == row) ? 1 : 0;
        }
    }
#pragma unroll
    for (int o = 16; o; o >>= 1) {
        lossv += __shfl_xor_sync(0xffffffffu, lossv, o);
        corr += __shfl_xor_sync(0xffffffffu, corr, o);
    }
    if (lane == 0) {
        red[wid] = lossv;
        ((int*)red)[16 + wid] = corr;
    }
    __syncthreads();
    if (tid == 0) {
        float s = 0.f;
        int ct = 0;
        for (int w = 0; w < 16; w++) { s += red[w]; ct += ((int*)red)[16 + w]; }
        atomicAdd(&g_loss, (double)s);
        atomicAdd(&g_cnt, ct);
    }
}

// ---------------- finalize scalars ----------------
__global__ void k_fin(float* out) {
    const double n = (double)KS * TP * BB;
    out[0] = (float)(g_loss / n);
    out[1] = (float)(100.0 * (double)g_cnt / n);
}

// ---------------- copy z_seq, c_seq into d_out ----------------
__global__ void k_copy(float* out, long long out_size) {
    size_t i0 = (size_t)blockIdx.x * blockDim.x + threadIdx.x;
    size_t stride = (size_t)gridDim.x * blockDim.x;
    const size_t NZ = (size_t)BB * TT * DD;
    const size_t NC = (size_t)BB * TT * CC;
    size_t avail = (out_size > 2) ? (size_t)(out_size - 2) : 0;
    size_t nz = NZ < avail ? NZ : avail;
    size_t nc2 = (avail > NZ) ? ((NC < avail - NZ) ? NC : avail - NZ) : 0;
    float2* oz = (float2*)(out + 2);
    const float2* z2 = (const float2*)g_z;
    for (size_t i = i0; i < nz / 2; i += stride) oz[i] = z2[i];
    float2* oc = (float2*)(out + 2 + NZ);
    const float2* c2 = (const float2*)g_c;
    for (size_t i = i0; i < nc2 / 2; i += stride) oc[i] = c2[i];
}

extern "C" void kernel_launch(void* const* d_in, const int* in_sizes, int n_in,
                              void* d_out, int out_size) {
    const float* rr  = (const float*)d_in[0];
    const float* We  = (const float*)d_in[1];
    const float* be  = (const float*)d_in[2];
    const float* Wi  = (const float*)d_in[3];
    const float* Wh  = (const float*)d_in[4];
    const float* bi  = (const float*)d_in[5];
    const float* bh  = (const float*)d_in[6];
    const float* Wkw = (const float*)d_in[7];
    const float* Wkb = (const float*)d_in[8];
    float* out = (float*)d_out;

    cudaFuncSetAttribute(k_gru3, cudaFuncAttributeMaxDynamicSharedMemorySize, GRU3_SMEM);
    cudaFuncSetAttribute(k_loss, cudaFuncAttributeMaxDynamicSharedMemorySize, LOSS_SMEM);

    k_z<<<dim3(TT / 64, BB), 128>>>(rr, We, be, Wh);      // + init + Wh transpose
    k_xproj<<<dim3(6, (BB * TT) / 128), 256>>>(Wi, bi);
    k_gru3<<<dim3(8, 16), 256, GRU3_SMEM>>>(bh);
    k_loss<<<dim3(TP, KS), 512, LOSS_SMEM>>>(Wkw, Wkb);
    k_fin<<<1, 1>>>(out);
    k_copy<<<2048, 256>>>(out, (long long)out_size);
}

// round 15
// speedup vs baseline: 1.3142x; 1.3142x over previous
#include <cuda_runtime.h>
#include <math.h>

#define BB 128
#define TT 512
#define WW 64
#define DD 128
#define CC 256
#define KS 12
#define TP 500

typedef unsigned long long ull;
typedef unsigned int uint;

// ---------------- device scratch (no runtime allocation allowed) ----------------
__device__ float g_z[(size_t)BB * TT * DD];        // 33.5 MB  (B,T,D) normalized z
__device__ float g_xp[(size_t)BB * TT * 3 * CC];   // 201 MB   (B,T,768) x_proj
__device__ float g_c[(size_t)BB * TT * CC];        // 67 MB    (B,T,C) GRU hidden states
__device__ float g_whT[3 * CC * CC];               // Wh transposed: [col][k]
__device__ double g_loss;
__device__ int    g_cnt;
__device__ unsigned g_sync[16];                    // per-rowgroup step counters

__device__ __forceinline__ uint f2tf(float f) {
    uint u;
    asm("cvt.rna.tf32.f32 %0, %1;" : "=r"(u) : "f"(f));
    return u;
}
__device__ __forceinline__ ull ffma2(ull a, ull b, ull c) {
    ull d;
    asm("fma.rn.f32x2 %0, %1, %2, %3;" : "=l"(d) : "l"(a), "l"(b), "l"(c));
    return d;
}
__device__ __forceinline__ ull packf2(float lo, float hi) {
    ull d;
    asm("mov.b64 %0, {%1, %2};" : "=l"(d) : "f"(lo), "f"(hi));
    return d;
}
__device__ __forceinline__ float pairsum(ull v) {
    float lo, hi;
    asm("mov.b64 {%0, %1}, %2;" : "=f"(lo), "=f"(hi) : "l"(v));
    return lo + hi;
}
__device__ __forceinline__ void unpackf2(ull v, float& lo, float& hi) {
    asm("mov.b64 {%0, %1}, %2;" : "=f"(lo), "=f"(hi) : "l"(v));
}
#define MMA_TF32(d, a, b) \
    asm volatile("mma.sync.aligned.m16n8k8.row.col.f32.tf32.tf32.f32 " \
                 "{%0,%1,%2,%3},{%4,%5,%6,%7},{%8,%9},{%0,%1,%2,%3};" \
                 : "+f"((d)[0]), "+f"((d)[1]), "+f"((d)[2]), "+f"((d)[3]) \
                 : "r"((a)[0]), "r"((a)[1]), "r"((a)[2]), "r"((a)[3]), \
                   "r"((b)[0]), "r"((b)[1]))

// ---------------- z = l2norm(rr @ We + be)  (+ fused init + Wh transpose) ----------------
__global__ __launch_bounds__(128) void k_z(const float* __restrict__ rr,
                                           const float* __restrict__ We,
                                           const float* __restrict__ be,
                                           const float* __restrict__ Wh) {
    __shared__ float Wes[64 * 128];
    __shared__ float rs[64];
    __shared__ float red[4];
    int b = blockIdx.y;
    int t0 = blockIdx.x << 6;
    int tid = threadIdx.x;

    int gb = blockIdx.y * 8 + blockIdx.x;
    int gtid = gb * 128 + tid;
    if (gtid == 0) {
        g_loss = 0.0; g_cnt = 0;
        for (int i = 0; i < 16; i++) g_sync[i] = 0u;
    }
    for (int i = gtid; i < 3 * CC * CC; i += 131072) {
        int kk = i & 255;
        int col = i >> 8;
        g_whT[i] = Wh[(size_t)kk * 768 + col];
    }

    for (int i = tid; i < 64 * 128; i += 128) Wes[i] = We[i];
    float bias = be[tid];
    __syncthreads();
    for (int tt = 0; tt < 64; tt++) {
        int t = t0 + tt;
        if (tid < 64) rs[tid] = rr[((size_t)b * TT + t) * WW + tid];
        __syncthreads();
        float acc = bias;
#pragma unroll
        for (int w = 0; w < 64; w++) acc += rs[w] * Wes[w * 128 + tid];
        float ss = acc * acc;
#pragma unroll
        for (int o = 16; o; o >>= 1) ss += __shfl_xor_sync(0xffffffffu, ss, o);
        if ((tid & 31) == 0) red[tid >> 5] = ss;
        __syncthreads();
        float tot = red[0] + red[1] + red[2] + red[3];
        float scale = 1.0f / fmaxf(sqrtf(tot), 1e-12f);
        g_z[((size_t)b * TT + t) * DD + tid] = acc * scale;
        __syncthreads();
    }
}

// ---------------- x_proj = z @ Wi + bi  (M=65536, N=768, K=128), FFMA2 ----------------
__global__ __launch_bounds__(256) void k_xproj(const float* __restrict__ Wi,
                                               const float* __restrict__ bi) {
    __shared__ float As[32 * 132];
    __shared__ float Bs[32 * 132];
    int tid = threadIdx.x;
    int tx = tid & 15, ty = tid >> 4;
    int m0 = blockIdx.y << 7, n0 = blockIdx.x << 7;
    ull accp[8][4];
#pragma unroll
    for (int i = 0; i < 8; i++)
#pragma unroll
        for (int p = 0; p < 4; p++) accp[i][p] = 0ull;

    for (int kc = 0; kc < DD; kc += 32) {
        for (int i = tid; i < 4096; i += 256) {
            int r = i >> 5, kk = i & 31;
            As[kk * 132 + r] = g_z[(size_t)(m0 + r) * DD + kc + kk];
        }
        for (int i = tid; i < 4096; i += 256) {
            int kk = i >> 7, n = i & 127;
            Bs[kk * 132 + n] = Wi[(size_t)(kc + kk) * 768 + n0 + n];
        }
        __syncthreads();
#pragma unroll
        for (int kk = 0; kk < 32; kk++) {
            float4 a1 = *(const float4*)&As[kk * 132 + ty * 4];
            float4 a2 = *(const float4*)&As[kk * 132 + 64 + ty * 4];
            ulonglong2 B1 = *(const ulonglong2*)&Bs[kk * 132 + tx * 4];
            ulonglong2 B2 = *(const ulonglong2*)&Bs[kk * 132 + 64 + tx * 4];
            float av[8] = {a1.x, a1.y, a1.z, a1.w, a2.x, a2.y, a2.z, a2.w};
#pragma unroll
            for (int i = 0; i < 8; i++) {
                ull a2i = packf2(av[i], av[i]);
                accp[i][0] = ffma2(a2i, B1.x, accp[i][0]);
                accp[i][1] = ffma2(a2i, B1.y, accp[i][1]);
                accp[i][2] = ffma2(a2i, B2.x, accp[i][2]);
                accp[i][3] = ffma2(a2i, B2.y, accp[i][3]);
            }
        }
        __syncthreads();
    }
#pragma unroll
    for (int i = 0; i < 8; i++) {
        int r = m0 + ((i < 4) ? ty * 4 + i : 64 + ty * 4 + i - 4);
#pragma unroll
        for (int p = 0; p < 4; p++) {
            int j0 = 2 * p;
            float lo, hi;
            unpackf2(accp[i][p], lo, hi);
            int c0 = n0 + ((j0 < 4) ? tx * 4 + j0 : 64 + tx * 4 + j0 - 4);
            g_xp[(size_t)r * 768 + c0]     = lo + bi[c0];
            g_xp[(size_t)r * 768 + c0 + 1] = hi + bi[c0 + 1];
        }
    }
}

// ---------------- persistent GRU: all 512 steps, atomic-flag sync (R13) ----------------
#define GRU2_SMEM ((96 * 256 + 8 * 256 + 8 * 3 * 256) * 4)
__global__ __launch_bounds__(256, 1) void k_gru2(const float* __restrict__ bh) {
    extern __shared__ float sm[];
    float* ws   = sm;                          // [96 cols][64 float4], XOR-swizzled
    float* hs   = sm + 96 * 256;               // [8][256]   h_{t-1}
    float* part = sm + 96 * 256 + 8 * 256;     // [8][3][256] k-octant partials

    int tid = threadIdx.x;
    int cgx = blockIdx.x;
    int rg  = blockIdx.y;
    int cb0 = cgx << 5;
    int rb0 = rg << 3;

    for (int i = tid; i < 96 * 64; i += 256) {
        int bc = i >> 6, kgrp = i & 63;
        int gate = bc >> 5, ch = bc & 31;
        float4 v = *(const float4*)&g_whT[(size_t)(gate * 256 + cb0 + ch) * 256 + kgrp * 4];
        *(float4*)&ws[(bc * 64 + (kgrp ^ (bc & 7))) * 4] = v;
    }

    int uc = tid & 31;
    int kh = tid >> 5;
    int cg = cb0 + uc;
    float bhr = bh[cg], bhz = bh[256 + cg], bhn = bh[512 + cg];

    int ur = kh;
    int b  = rb0 + ur;
    const float* xpb = g_xp + (size_t)b * TT * 768;
    float* crow = g_c + (size_t)b * TT * CC;

    int sflat = tid * 8;
    int sr = sflat >> 8, skk = sflat & 255;

    const ulonglong2* ws4 = (const ulonglong2*)ws;
    int s7 = uc & 7;
    int wb0 = (0  + uc) * 64 + kh * 8;
    int wb1 = (32 + uc) * 64 + kh * 8;
    int wb2 = (64 + uc) * 64 + kh * 8;

    for (int t = 0; t < TT; t++) {
        if (t == 0) {
            *(float4*)&hs[sflat]     = make_float4(0.f, 0.f, 0.f, 0.f);
            *(float4*)&hs[sflat + 4] = make_float4(0.f, 0.f, 0.f, 0.f);
        } else {
            const float4* s =
                (const float4*)&g_c[((size_t)(rb0 + sr) * TT + (t - 1)) * CC + skk];
            *(float4*)&hs[sflat]     = __ldcg(s);
            *(float4*)&hs[sflat + 4] = __ldcg(s + 1);
        }
        float xr = __ldg(&xpb[(size_t)t * 768 + cg]);
        float xz = __ldg(&xpb[(size_t)t * 768 + 256 + cg]);
        float xn = __ldg(&xpb[(size_t)t * 768 + 512 + cg]);
        __syncthreads();

        ull p0[8], p1[8], p2[8];
#pragma unroll
        for (int r = 0; r < 8; r++) { p0[r] = 0ull; p1[r] = 0ull; p2[r] = 0ull; }
#pragma unroll
        for (int j = 0; j < 8; j++) {
            int js = j ^ s7;
            ulonglong2 W0 = ws4[wb0 + js];
            ulonglong2 W1 = ws4[wb1 + js];
            ulonglong2 W2 = ws4[wb2 + js];
            int kofs = kh * 32 + j * 4;
#pragma unroll
            for (int r = 0; r < 8; r++) {
                ulonglong2 H = *(const ulonglong2*)&hs[r * 256 + kofs];
                p0[r] = ffma2(H.x, W0.x, p0[r]);
                p0[r] = ffma2(H.y, W0.y, p0[r]);
                p1[r] = ffma2(H.x, W1.x, p1[r]);
                p1[r] = ffma2(H.y, W1.y, p1[r]);
                p2[r] = ffma2(H.x, W2.x, p2[r]);
                p2[r] = ffma2(H.y, W2.y, p2[r]);
            }
        }
#pragma unroll
        for (int r = 0; r < 8; r++) {
            part[(r * 3 + 0) * 256 + kh * 32 + uc] = pairsum(p0[r]);
            part[(r * 3 + 1) * 256 + kh * 32 + uc] = pairsum(p1[r]);
            part[(r * 3 + 2) * 256 + kh * 32 + uc] = pairsum(p2[r]);
        }
        __syncthreads();

        {
            float hr = bhr, hz = bhz, hn = bhn;
#pragma unroll
            for (int q = 0; q < 8; q++) {
                hr += part[(ur * 3 + 0) * 256 + q * 32 + uc];
                hz += part[(ur * 3 + 1) * 256 + q * 32 + uc];
                hn += part[(ur * 3 + 2) * 256 + q * 32 + uc];
            }
            float rgt = 1.f / (1.f + expf(-(xr + hr)));
            float zgt = 1.f / (1.f + expf(-(xz + hz)));
            float ngt = tanhf(xn + rgt * hn);
            float hp = hs[ur * 256 + cg];
            crow[(size_t)t * CC + cg] = (1.f - zgt) * ngt + zgt * hp;
        }

        __syncthreads();
        if (tid == 0) {
            asm volatile("red.release.gpu.global.add.u32 [%0], %1;"
                         :: "l"(&g_sync[rg]), "r"(1u) : "memory");
            unsigned target = 8u * (unsigned)(t + 1);
            unsigned v;
            do {
                asm volatile("ld.acquire.gpu.u32 %0, [%1];"
                             : "=r"(v) : "l"(&g_sync[rg]) : "memory");
            } while (v < target);
        }
        __syncthreads();
    }
}

// ---------------- fused loss: tf32 mma, 512 threads, pipelined fragments ----------------
// Stage-1/2 fragment LDS double-buffered: next-ks fragments issue before the
// current-ks MMAs, overlapping LDS latency with tensor work (occ-1 hides
// nothing otherwise). Same values, same accumulation order -> bit-exact logits.
#define LOSS_SMEM ((128 * 132 + 128 * 132 + 128 + 64) * 4)

#define S1_LOAD(buf, k0) do { \
    _Pragma("unroll") \
    for (int mt = 0; mt < 2; mt++) { \
        int r = R0 + mt * 16 + g; \
        af[buf][mt][0] = __float_as_uint(As[r * 36 + (k0) + tq]); \
        af[buf][mt][1] = __float_as_uint(As[(r + 8) * 36 + (k0) + tq]); \
        af[buf][mt][2] = __float_as_uint(As[r * 36 + (k0) + tq + 4]); \
        af[buf][mt][3] = __float_as_uint(As[(r + 8) * 36 + (k0) + tq + 4]); \
    } \
    _Pragma("unroll") \
    for (int nt = 0; nt < 4; nt++) { \
        int c = C0 + nt * 8 + g; \
        bf[buf][nt][0] = __float_as_uint(Bs[((k0) + tq) * 136 + c]); \
        bf[buf][nt][1] = __float_as_uint(Bs[((k0) + tq + 4) * 136 + c]); \
    } \
} while (0)

#define S2_LOAD(buf, k0) do { \
    _Pragma("unroll") \
    for (int mt = 0; mt < 2; mt++) { \
        int r = R0 + mt * 16 + g; \
        af[buf][mt][0] = __float_as_uint(Psm[r * 132 + (k0) + tq]); \
        af[buf][mt][1] = __float_as_uint(Psm[(r + 8) * 132 + (k0) + tq]); \
        af[buf][mt][2] = __float_as_uint(Psm[r * 132 + (k0) + tq + 4]); \
        af[buf][mt][3] = __float_as_uint(Psm[(r + 8) * 132 + (k0) + tq + 4]); \
    } \
    _Pragma("unroll") \
    for (int nt = 0; nt < 4; nt++) { \
        int c = C0 + nt * 8 + g; \
        bf[buf][nt][0] = __float_as_uint(Zsm[c * 132 + (k0) + tq]); \
        bf[buf][nt][1] = __float_as_uint(Zsm[c * 132 + (k0) + tq + 4]); \
    } \
} while (0)

#define S_MMA(accv, buf) do { \
    _Pragma("unroll") \
    for (int mt = 0; mt < 2; mt++) \
        _Pragma("unroll") \
        for (int nt = 0; nt < 4; nt++) \
            MMA_TF32(accv[mt][nt], af[buf][mt], bf[buf][nt]); \
} while (0)

__global__ __launch_bounds__(512) void k_loss(const float* __restrict__ Wkw,
                                              const float* __restrict__ Wkb) {
    extern __shared__ float sm[];
    float* Psm = sm;                     // [128][132]
    float* As  = sm + 128 * 132;         // [128][36]  (stage1 A, tf32)
    float* Bs  = As + 128 * 36;          // [32][136]  (stage1 B, tf32)
    float* Zsm = sm + 128 * 132;         // [128][132] (stage2, aliases As/Bs)
    float* rnorm = sm + 2 * 128 * 132;
    float* red = rnorm + 128;            // 16 floats + 16 ints

    int t = blockIdx.x, k = blockIdx.y;
    int tid = threadIdx.x;
    int lane = tid & 31, wid = tid >> 5;
    int g = lane >> 2, tq = lane & 3;
    int R0 = (wid >> 2) * 32;
    int C0 = (wid & 3) * 32;

    int ar[8], ak[8], bk[8], bd[8];
#pragma unroll
    for (int j = 0; j < 8; j++) {
        int i = tid + j * 512;
        ar[j] = i >> 5;  ak[j] = i & 31;
        bk[j] = i >> 7;  bd[j] = i & 127;
    }

    uint af[2][2][4], bf[2][4][2];       // double-buffered fragments

    // ======== stage 1: P = c_t @ Wk[k]  (128x128, K=256), tf32 mma ========
    float acc[2][4][4];
#pragma unroll
    for (int mt = 0; mt < 2; mt++)
#pragma unroll
        for (int nt = 0; nt < 4; nt++)
#pragma unroll
            for (int i = 0; i < 4; i++) acc[mt][nt][i] = 0.f;

    float ra[8], rb[8];
#pragma unroll
    for (int j = 0; j < 8; j++) {
        ra[j] = g_c[((size_t)ar[j] * TT + t) * CC + ak[j]];
        rb[j] = Wkw[((size_t)k * CC + bk[j]) * DD + bd[j]];
    }

    for (int kc = 0; kc < CC; kc += 32) {
#pragma unroll
        for (int j = 0; j < 8; j++) {
            As[ar[j] * 36 + ak[j]]  = __uint_as_float(f2tf(ra[j]));
            Bs[bk[j] * 136 + bd[j]] = __uint_as_float(f2tf(rb[j]));
        }
        __syncthreads();
        if (kc + 32 < CC) {
#pragma unroll
            for (int j = 0; j < 8; j++) {
                ra[j] = g_c[((size_t)ar[j] * TT + t) * CC + kc + 32 + ak[j]];
                rb[j] = Wkw[((size_t)k * CC + kc + 32 + bk[j]) * DD + bd[j]];
            }
        }
        // pipelined: fragments(ks+1) load while MMAs(ks) execute
        S1_LOAD(0, 0);
        S1_LOAD(1, 8);
        S_MMA(acc, 0);
        S1_LOAD(0, 16);
        S_MMA(acc, 1);
        S1_LOAD(1, 24);
        S_MMA(acc, 0);
        S_MMA(acc, 1);
        __syncthreads();
    }

    // epilogue: +bias, round to tf32, stash in Psm (stage2 A-operand)
#pragma unroll
    for (int nt = 0; nt < 4; nt++) {
        int c0 = C0 + nt * 8 + 2 * tq;
        float bia0 = __ldg(&Wkb[k * DD + c0]);
        float bia1 = __ldg(&Wkb[k * DD + c0 + 1]);
#pragma unroll
        for (int mt = 0; mt < 2; mt++) {
            int r = R0 + mt * 16 + g;
            Psm[r * 132 + c0]           = __uint_as_float(f2tf(acc[mt][nt][0] + bia0));
            Psm[r * 132 + c0 + 1]       = __uint_as_float(f2tf(acc[mt][nt][1] + bia1));
            Psm[(r + 8) * 132 + c0]     = __uint_as_float(f2tf(acc[mt][nt][2] + bia0));
            Psm[(r + 8) * 132 + c0 + 1] = __uint_as_float(f2tf(acc[mt][nt][3] + bia1));
        }
    }
    __syncthreads();

    // load zf tile (tf32-rounded): Z[c][d] = z[c, t+k+1, d]
    for (int i = tid; i < 16384; i += 512) {
        int cidx = i >> 7, d = i & 127;
        Zsm[cidx * 132 + d] =
            __uint_as_float(f2tf(g_z[((size_t)cidx * TT + t + k + 1) * DD + d]));
    }
    // per-row 1/||P||
    if (tid < 128) {
        const float4* pp = (const float4*)&Psm[tid * 132];
        float ss = 0.f;
#pragma unroll
        for (int q = 0; q < 32; q++) {
            float4 v = pp[q];
            ss += v.x * v.x + v.y * v.y + v.z * v.z + v.w * v.w;
        }
        rnorm[tid] = 1.f / fmaxf(sqrtf(ss), 1e-12f);
    }
    __syncthreads();

    // ======== stage 2: S = P @ Z^T  (128x128, K=128), tf32 mma, pipelined ========
    float acc2[2][4][4];
#pragma unroll
    for (int mt = 0; mt < 2; mt++)
#pragma unroll
        for (int nt = 0; nt < 4; nt++)
#pragma unroll
            for (int i = 0; i < 4; i++) acc2[mt][nt][i] = 0.f;

    S2_LOAD(0, 0);
#pragma unroll
    for (int ks = 0; ks < 16; ks++) {
        int cur = ks & 1;
        if (ks < 15) {
            if (cur) { S2_LOAD(0, (ks + 1) * 8); }
            else     { S2_LOAD(1, (ks + 1) * 8); }
        }
        S_MMA(acc2, cur);
    }
    __syncthreads();   // all Psm reads done before logits overwrite

    // logits = rnorm[b] * S / TEMP  -> Psm (fp32)
#pragma unroll
    for (int mt = 0; mt < 2; mt++) {
        int r = R0 + mt * 16 + g;
        float rn0 = rnorm[r] * 10.0f;
        float rn1 = rnorm[r + 8] * 10.0f;
#pragma unroll
        for (int nt = 0; nt < 4; nt++) {
            int c0 = C0 + nt * 8 + 2 * tq;
            Psm[r * 132 + c0]           = acc2[mt][nt][0] * rn0;
            Psm[r * 132 + c0 + 1]       = acc2[mt][nt][1] * rn0;
            Psm[(r + 8) * 132 + c0]     = acc2[mt][nt][2] * rn1;
            Psm[(r + 8) * 132 + c0 + 1] = acc2[mt][nt][3] * rn1;
        }
    }
    __syncthreads();

    // per-row LSE, diag, argmax: 4 lanes per row
    float lossv = 0.f;
    int corr = 0;
    {
        int row = tid >> 2, sub = tid & 3;
        const float* L = &Psm[row * 132];
        int c0 = sub * 32;
        float m = -1e30f;
        int am = 0;
        for (int cc = c0; cc < c0 + 32; cc++) {
            float v = L[cc];
            if (v > m) { m = v; am = cc; }
        }
#pragma unroll
        for (int o = 1; o <= 2; o <<= 1) {
            float om = __shfl_xor_sync(0xffffffffu, m, o);
            int oa = __shfl_xor_sync(0xffffffffu, am, o);
            if (om > m || (om == m && oa < am)) { m = om; am = oa; }
        }
        float s = 0.f;
        for (int cc = c0; cc < c0 + 32; cc++) s += expf(L[cc] - m);
#pragma unroll
        for (int o = 1; o <= 2; o <<= 1) s += __shfl_xor_sync(0xffffffffu, s, o);
        if (sub == 0) {
            lossv = m + logf(s) - L[row];
            corr = (am == row) ? 1 : 0;
        }
    }
#pragma unroll
    for (int o = 16; o; o >>= 1) {
        lossv += __shfl_xor_sync(0xffffffffu, lossv, o);
        corr += __shfl_xor_sync(0xffffffffu, corr, o);
    }
    if (lane == 0) {
        red[wid] = lossv;
        ((int*)red)[16 + wid] = corr;
    }
    __syncthreads();
    if (tid == 0) {
        float s = 0.f;
        int ct = 0;
        for (int w = 0; w < 16; w++) { s += red[w]; ct += ((int*)red)[16 + w]; }
        atomicAdd(&g_loss, (double)s);
        atomicAdd(&g_cnt, ct);
    }
}

// ---------------- finalize scalars ----------------
__global__ void k_fin(float* out) {
    const double n = (double)KS * TP * BB;
    out[0] = (float)(g_loss / n);
    out[1] = (float)(100.0 * (double)g_cnt / n);
}

// ---------------- copy z_seq, c_seq into d_out ----------------
__global__ void k_copy(float* out, long long out_size) {
    size_t i0 = (size_t)blockIdx.x * blockDim.x + threadIdx.x;
    size_t stride = (size_t)gridDim.x * blockDim.x;
    const size_t NZ = (size_t)BB * TT * DD;
    const size_t NC = (size_t)BB * TT * CC;
    size_t avail = (out_size > 2) ? (size_t)(out_size - 2) : 0;
    size_t nz = NZ < avail ? NZ : avail;
    size_t nc2 = (avail > NZ) ? ((NC < avail - NZ) ? NC : avail - NZ) : 0;
    float2* oz = (float2*)(out + 2);
    const float2* z2 = (const float2*)g_z;
    for (size_t i = i0; i < nz / 2; i += stride) oz[i] = z2[i];
    float2* oc = (float2*)(out + 2 + NZ);
    const float2* c2 = (const float2*)g_c;
    for (size_t i = i0; i < nc2 / 2; i += stride) oc[i] = c2[i];
}

extern "C" void kernel_launch(void* const* d_in, const int* in_sizes, int n_in,
                              void* d_out, int out_size) {
    const float* rr  = (const float*)d_in[0];
    const float* We  = (const float*)d_in[1];
    const float* be  = (const float*)d_in[2];
    const float* Wi  = (const float*)d_in[3];
    const float* Wh  = (const float*)d_in[4];
    const float* bi  = (const float*)d_in[5];
    const float* bh  = (const float*)d_in[6];
    const float* Wkw = (const float*)d_in[7];
    const float* Wkb = (const float*)d_in[8];
    float* out = (float*)d_out;

    cudaFuncSetAttribute(k_gru2, cudaFuncAttributeMaxDynamicSharedMemorySize, GRU2_SMEM);
    cudaFuncSetAttribute(k_loss, cudaFuncAttributeMaxDynamicSharedMemorySize, LOSS_SMEM);

    k_z<<<dim3(TT / 64, BB), 128>>>(rr, We, be, Wh);      // + init + Wh transpose
    k_xproj<<<dim3(6, (BB * TT) / 128), 256>>>(Wi, bi);
    k_gru2<<<dim3(8, 16), 256, GRU2_SMEM>>>(bh);
    k_loss<<<dim3(TP, KS), 512, LOSS_SMEM>>>(Wkw, Wkb);
    k_fin<<<1, 1>>>(out);
    k_copy<<<2048, 256>>>(out, (long long)out_size);
}